// round 12
// baseline (speedup 1.0000x reference)
#include <cuda_runtime.h>
#include <math.h>

#define Bsz 16
#define Ssz 1024
#define Hsz 768
#define NHs 12
#define Dh  64
#define FFs 3072

// ---------------- scratch (device globals; no allocation) ----------------
__device__ float d_q0p[24*Bsz*Hsz];
__device__ float d_u[Bsz*NHs*Hsz];            // prescaled by 1/8
__device__ float d_qbk[Bsz*NHs];
__device__ float d_cmax[Bsz*NHs*16];
__device__ float d_csum[Bsz*NHs*16];
__device__ float d_fbp[16*Bsz*NHs*Hsz];
__device__ float d_fbar[Bsz*NHs*Hsz];         // normalized fbar
__device__ float d_ctxp[24*Bsz*Hsz];
__device__ float d_yp[24*Bsz*Hsz];
__device__ float d_attn0[Bsz*Hsz];
__device__ float d_gpart[32*Bsz*FFs];
__device__ float d_opart[48*Bsz*Hsz];
__device__ float d_hid[Bsz*Hsz];
__device__ float d_pp[24*Bsz*Hsz];
__device__ float d_prefsink[112*256];

typedef unsigned long long ull;

// ---------------- f32x2 packed math ----------------
__device__ __forceinline__ ull ffma2(ull a, ull b, ull c){
  ull d; asm("fma.rn.f32x2 %0, %1, %2, %3;" : "=l"(d) : "l"(a), "l"(b), "l"(c)); return d;
}
__device__ __forceinline__ ull pk2(float lo, float hi){
  ull r; asm("mov.b64 %0, {%1, %2};" : "=l"(r) : "f"(lo), "f"(hi)); return r;
}
__device__ __forceinline__ void upk2(float& lo, float& hi, ull v){
  asm("mov.b64 {%0, %1}, %2;" : "=f"(lo), "=f"(hi) : "l"(v));
}

__device__ __forceinline__ float block_sum(float v, float* red){
  int lane = threadIdx.x & 31, w = threadIdx.x >> 5;
  #pragma unroll
  for (int o = 16; o; o >>= 1) v += __shfl_xor_sync(0xffffffffu, v, o);
  if (lane == 0) red[w] = v;
  __syncthreads();
  float s = (lane < 8) ? red[lane] : 0.f;
  #pragma unroll
  for (int o = 16; o; o >>= 1) s += __shfl_xor_sync(0xffffffffu, s, o);
  __syncthreads();
  return s;
}

// grid-stride L2-warm of one tensor (prefetch blocks only)
__device__ __forceinline__ float prefsum(const float* p, int n4, int pb, int np, int t){
  const float4* p4 = reinterpret_cast<const float4*>(p);
  float a = 0.f;
  for (int i = pb*256 + t; i < n4; i += np*256){
    float4 v = __ldg(p4 + i);
    a += v.x + v.y + v.z + v.w;
  }
  return a;
}

// ============ K1: q0 partials (144 compute blocks) + FEATURES prefetch (112) ============
__global__ void kq0p(const float* __restrict__ f, const float* __restrict__ wq,
                     const float* __restrict__ bq){
  __shared__ float sf[512];
  const int t = threadIdx.x, bid = blockIdx.x;
  if (bid >= 144){
    int pb = bid - 144;
    d_prefsink[pb*256 + t] = prefsum(f, 3145728, pb, 112, t);   // 50 MB features
    return;
  }
  int jc = bid % 6, ks = bid / 6;                // ks 0..23
  int j0 = jc*128, i0 = ks*32;
  #pragma unroll
  for (int k = 0; k < 2; k++){
    int v = t + 256*k;                           // 512 = 16b x 32i
    sf[v] = f[(size_t)(v>>5)*Ssz*Hsz + i0 + (v&31)];
  }
  __syncthreads();
  int j = j0 + (t & 127), bh = t >> 7;
  float binit = (ks == 0) ? bq[j] : 0.f;
  float acc[8];
  #pragma unroll
  for (int bb = 0; bb < 8; bb++) acc[bb] = binit;
  #pragma unroll 8
  for (int i = 0; i < 32; i++){
    float w = wq[(size_t)(i0+i)*Hsz + j];
    #pragma unroll
    for (int bb = 0; bb < 8; bb++)
      acc[bb] = fmaf(sf[(bh*8+bb)*32 + i], w, acc[bb]);
  }
  #pragma unroll
  for (int bb = 0; bb < 8; bb++)
    d_q0p[ks*(Bsz*Hsz) + (bh*8+bb)*Hsz + j] = acc[bb];
}

// ============ K2: u = Wk q0 / 8 ; qbk (72 compute) + wv,wo prefetch (112) ============
__global__ void ku(const float* __restrict__ wk, const float* __restrict__ bk,
                   const float* __restrict__ wv, const float* __restrict__ wo){
  __shared__ float sf[1024];
  const int t = threadIdx.x, bid = blockIdx.x;
  if (bid >= 72){
    int pb = bid - 72;
    float a = prefsum(wv, 147456, pb, 112, t) + prefsum(wo, 147456, pb, 112, t);
    d_prefsink[pb*256 + t] = a;
    return;
  }
  int h = bid % 12, ic = bid / 12;
  #pragma unroll
  for (int k = 0; k < 4; k++){
    int v = t + 256*k;
    float s = 0.f;
    #pragma unroll
    for (int p = 0; p < 24; p++)
      s += d_q0p[p*(Bsz*Hsz) + (v>>6)*Hsz + h*Dh + (v&63)];
    sf[v] = s;
  }
  __syncthreads();
  if (ic == 0 && t < Bsz){
    float s = 0.f;
    for (int d = 0; d < Dh; d++) s += sf[t*Dh + d]*bk[h*Dh + d];
    d_qbk[t*NHs + h] = s * 0.125f;
  }
  int i = ic*128 + (t & 127), bh = t >> 7;
  const float4* wr = reinterpret_cast<const float4*>(wk + (size_t)i*Hsz + h*Dh);
  float acc[8] = {0,0,0,0,0,0,0,0};
  #pragma unroll
  for (int d4 = 0; d4 < Dh/4; d4++){
    float4 w = wr[d4];
    #pragma unroll
    for (int bb = 0; bb < 8; bb++){
      float4 q = *reinterpret_cast<const float4*>(&sf[(bh*8+bb)*Dh + d4*4]);
      acc[bb] = fmaf(w.x,q.x, fmaf(w.y,q.y, fmaf(w.z,q.z, fmaf(w.w,q.w, acc[bb]))));
    }
  }
  #pragma unroll
  for (int bb = 0; bb < 8; bb++)
    d_u[((bh*8+bb)*NHs + h)*Hsz + i] = acc[bb] * 0.125f;
}

// ===== K3: fused scores + chunk softmax + fbar partials (256) + w1,w2,wp prefetch (96) =====
__global__ void kattn(const float* __restrict__ f, const float* __restrict__ mask,
                      const float* __restrict__ w1, const float* __restrict__ w2,
                      const float* __restrict__ wp){
  __shared__ __align__(16) float sU[NHs*Hsz];      // 36 KB
  __shared__ __align__(16) float sS[768];
  const int t = threadIdx.x, bid = blockIdx.x;
  if (bid >= 256){
    int pb = bid - 256;
    float a = prefsum(w1, 589824, pb, 96, t) + prefsum(w2, 589824, pb, 96, t)
            + prefsum(wp, 147456, pb, 96, t);
    d_prefsink[pb*256 + t] = a;
    return;
  }
  int sc = bid & 15, b = bid >> 4;
  const float* ubase = d_u + (size_t)b*NHs*Hsz;
  const float* fbase = f + ((size_t)b*Ssz + sc*64)*Hsz;

  #pragma unroll
  for (int k = 0; k < NHs*Hsz/256; k++) sU[t + 256*k] = ubase[t + 256*k];
  __syncthreads();

  {
    int r = t >> 2, q = t & 3;
    ull acc2[NHs];
    #pragma unroll
    for (int h = 0; h < NHs; h++) acc2[h] = 0ull;
    const float* frow = fbase + (size_t)r*Hsz + q*8;
    #pragma unroll 4
    for (int ic = 0; ic < 24; ic++){
      ulonglong2 fv0 = *reinterpret_cast<const ulonglong2*>(frow + ic*32);
      ulonglong2 fv1 = *reinterpret_cast<const ulonglong2*>(frow + ic*32 + 4);
      #pragma unroll
      for (int h = 0; h < NHs; h++){
        const ull* up = reinterpret_cast<const ull*>(&sU[h*Hsz + ic*32 + q*8]);
        acc2[h] = ffma2(fv0.x, up[0], acc2[h]);
        acc2[h] = ffma2(fv0.y, up[1], acc2[h]);
        acc2[h] = ffma2(fv1.x, up[2], acc2[h]);
        acc2[h] = ffma2(fv1.y, up[3], acc2[h]);
      }
    }
    int srow = sc*64 + r;
    float mv = mask[b*Ssz + srow];
    #pragma unroll
    for (int h = 0; h < NHs; h++){
      float lo, hi; upk2(lo, hi, acc2[h]);
      float v = lo + hi;
      v += __shfl_xor_sync(0xffffffffu, v, 1);
      v += __shfl_xor_sync(0xffffffffu, v, 2);
      if (q == 0) sS[r*NHs + h] = v + d_qbk[b*NHs + h] + mv;
    }
  }
  __syncthreads();

  if (t < 192){
    int h = t >> 4, l16 = t & 15;
    float v0 = sS[(l16   )*NHs + h], v1 = sS[(l16+16)*NHs + h];
    float v2 = sS[(l16+32)*NHs + h], v3 = sS[(l16+48)*NHs + h];
    float m = fmaxf(fmaxf(v0,v1), fmaxf(v2,v3));
    #pragma unroll
    for (int o = 1; o < 16; o <<= 1) m = fmaxf(m, __shfl_xor_sync(0xffffffffu, m, o));
    float e0 = expf(v0-m), e1 = expf(v1-m), e2 = expf(v2-m), e3 = expf(v3-m);
    float s = e0+e1+e2+e3;
    #pragma unroll
    for (int o = 1; o < 16; o <<= 1) s += __shfl_xor_sync(0xffffffffu, s, o);
    sS[(l16   )*NHs + h] = e0; sS[(l16+16)*NHs + h] = e1;
    sS[(l16+32)*NHs + h] = e2; sS[(l16+48)*NHs + h] = e3;
    if (l16 == 0){
      d_cmax[(b*NHs + h)*16 + sc] = m;
      d_csum[(b*NHs + h)*16 + sc] = s;
    }
  }
  __syncthreads();

  if (t < 192){
    ull acc2[2*NHs];
    #pragma unroll
    for (int k = 0; k < 2*NHs; k++) acc2[k] = 0ull;
    const float* fb = fbase + t*4;
    #pragma unroll 4
    for (int s = 0; s < 64; s++){
      ulonglong2 fv = *reinterpret_cast<const ulonglong2*>(fb + (size_t)s*Hsz);
      #pragma unroll
      for (int h = 0; h < NHs; h++){
        float e = sS[s*NHs + h];
        ull pp = pk2(e, e);
        acc2[2*h]   = ffma2(pp, fv.x, acc2[2*h]);
        acc2[2*h+1] = ffma2(pp, fv.y, acc2[2*h+1]);
      }
    }
    #pragma unroll
    for (int h = 0; h < NHs; h++){
      float4 o;
      upk2(o.x, o.y, acc2[2*h]);
      upk2(o.z, o.w, acc2[2*h+1]);
      *reinterpret_cast<float4*>(
        &d_fbp[((size_t)(sc*Bsz + b)*NHs + h)*Hsz + t*4]) = o;
    }
  }
}

// ============ K4a: rescale-reduce fbar partials -> d_fbar (grid 192) ============
__global__ void kred(){
  const int t = threadIdx.x, bid = blockIdx.x;   // bid = b*12 + h
  int b = bid / NHs, h = bid % NHs;
  const float* cm = &d_cmax[bid*16];
  const float* cs = &d_csum[bid*16];
  float M = cm[0];
  #pragma unroll
  for (int sc = 1; sc < 16; sc++) M = fmaxf(M, cm[sc]);
  float w[16]; float den = 0.f;
  #pragma unroll
  for (int sc = 0; sc < 16; sc++){ w[sc] = expf(cm[sc]-M); den += cs[sc]*w[sc]; }
  float invd = 1.f/den;
  #pragma unroll
  for (int sc = 0; sc < 16; sc++) w[sc] *= invd;

  if (t < 192){
    float4 acc = make_float4(0.f,0.f,0.f,0.f);
    #pragma unroll
    for (int sc = 0; sc < 16; sc++){
      float4 v = *reinterpret_cast<const float4*>(
        &d_fbp[((size_t)(sc*Bsz + b)*NHs + h)*Hsz + t*4]);
      acc.x = fmaf(w[sc], v.x, acc.x);
      acc.y = fmaf(w[sc], v.y, acc.y);
      acc.z = fmaf(w[sc], v.z, acc.z);
      acc.w = fmaf(w[sc], v.w, acc.w);
    }
    *reinterpret_cast<float4*>(&d_fbar[(size_t)bid*Hsz + t*4]) = acc;
  }
}

// ============ K4b: ctx partials via wv (grid 144) ============
__global__ void kctx2(const float* __restrict__ wv){
  __shared__ float sf[1024];
  const int t = threadIdx.x, bid = blockIdx.x;
  int jc = bid % 6, ks = bid / 6;                // ks 0..23
  int j0 = jc*128, i0 = ks*32, h0 = jc*2;
  #pragma unroll
  for (int k = 0; k < 4; k++){
    int v = t + 256*k;                           // 1024 = 16bb x 2hl x 32i
    int bb = v>>6, hl = (v>>5)&1, i = v&31;
    sf[v] = d_fbar[(size_t)(bb*NHs + h0 + hl)*Hsz + i0 + i];
  }
  __syncthreads();
  int j = j0 + (t & 127), hl = (t & 127) >> 6, bh = t >> 7;
  float acc[8] = {0,0,0,0,0,0,0,0};
  #pragma unroll 8
  for (int i = 0; i < 32; i++){
    float w = wv[(size_t)(i0+i)*Hsz + j];
    #pragma unroll
    for (int bb = 0; bb < 8; bb++)
      acc[bb] = fmaf(sf[(bh*8+bb)*64 + hl*32 + i], w, acc[bb]);
  }
  #pragma unroll
  for (int bb = 0; bb < 8; bb++)
    d_ctxp[ks*(Bsz*Hsz) + (bh*8+bb)*Hsz + j] = acc[bb];
}

// ============ K5: y partials via wo (grid 144) ============
__global__ void kyp(const float* __restrict__ wo, const float* __restrict__ bv){
  __shared__ float sf[512];
  const int t = threadIdx.x, bid = blockIdx.x;
  int jc = bid % 6, ks = bid / 6;                // ks 0..23
  int j0 = jc*128, i0 = ks*32;
  #pragma unroll
  for (int k = 0; k < 2; k++){
    int v = t + 256*k;                           // 512 = 16b x 32i
    int bb = v>>5, i = v&31;
    float s = bv[i0 + i];
    #pragma unroll
    for (int p = 0; p < 24; p++)
      s += d_ctxp[p*(Bsz*Hsz) + bb*Hsz + i0 + i];
    sf[v] = s;
  }
  __syncthreads();
  int j = j0 + (t & 127), bh = t >> 7;
  float acc[8] = {0,0,0,0,0,0,0,0};
  #pragma unroll 8
  for (int i = 0; i < 32; i++){
    float w = wo[(size_t)(i0+i)*Hsz + j];
    #pragma unroll
    for (int bb = 0; bb < 8; bb++)
      acc[bb] = fmaf(sf[(bh*8+bb)*32 + i], w, acc[bb]);
  }
  #pragma unroll
  for (int bb = 0; bb < 8; bb++)
    d_yp[ks*(Bsz*Hsz) + (bh*8+bb)*Hsz + j] = acc[bb];
}

// ============ K6: LN1 (grid 16) ============
__global__ void kln1(const float* __restrict__ f, const float* __restrict__ bo,
                     const float* __restrict__ g1, const float* __restrict__ be1){
  __shared__ float sred[32];
  const int t = threadIdx.x, b = blockIdx.x;
  float yv[3];
  #pragma unroll
  for (int kk = 0; kk < 3; kk++){
    int j = t + 256*kk;
    float y = bo[j] + f[(size_t)b*Ssz*Hsz + j];
    #pragma unroll
    for (int ks = 0; ks < 24; ks++) y += d_yp[ks*(Bsz*Hsz) + b*Hsz + j];
    yv[kk] = y;
  }
  float mu = block_sum(yv[0]+yv[1]+yv[2], sred) * (1.f/Hsz);
  float ss = 0.f;
  #pragma unroll
  for (int kk = 0; kk < 3; kk++){ float d = yv[kk]-mu; ss += d*d; }
  float var = block_sum(ss, sred) * (1.f/Hsz);
  float inv = rsqrtf(var + 1e-12f);
  #pragma unroll
  for (int kk = 0; kk < 3; kk++){
    int j = t + 256*kk;
    d_attn0[b*Hsz + j] = (yv[kk]-mu) * inv * g1[j] + be1[j];
  }
}

// ============ K7: FFN1 partials (grid 384) ============
__global__ void kffn1(const float* __restrict__ w1){
  __shared__ ull sbuf[192];
  const int t = threadIdx.x, bid = blockIdx.x;
  int mc = bid % 12, is = bid / 12;              // is 0..31
  int m = mc*256 + t, i0 = is*24;
  if (t < 192){
    int bp = t / 24, i = t % 24;
    sbuf[t] = pk2(d_attn0[(2*bp)*Hsz + i0 + i], d_attn0[(2*bp+1)*Hsz + i0 + i]);
  }
  __syncthreads();
  ull acc2[8];
  #pragma unroll
  for (int k = 0; k < 8; k++) acc2[k] = 0ull;
  #pragma unroll 8
  for (int i = 0; i < 24; i++){
    float w = w1[(size_t)(i0+i)*FFs + m];
    ull wpk = pk2(w, w);
    #pragma unroll
    for (int bp = 0; bp < 8; bp++)
      acc2[bp] = ffma2(sbuf[bp*24 + i], wpk, acc2[bp]);
  }
  #pragma unroll
  for (int bp = 0; bp < 8; bp++){
    float lo, hi; upk2(lo, hi, acc2[bp]);
    d_gpart[(size_t)(is*Bsz + 2*bp)*FFs + m]   = lo;
    d_gpart[(size_t)(is*Bsz + 2*bp+1)*FFs + m] = hi;
  }
}

// ============ K8: fused gelu-reduce + FFN2 partials (grid 144) ============
__global__ void kffn2(const float* __restrict__ b1, const float* __restrict__ w2){
  __shared__ ull sbuf[512];
  const int t = threadIdx.x, bid = blockIdx.x;
  int jc = bid % 3, ms = bid / 3;                // ms 0..47
  int j = jc*256 + t, m0 = ms*64;
  for (int n = t; n < 512; n += 256){            // 512 = 8bp x 64mm
    int bp = n >> 6, mm = n & 63;
    float gv0 = b1[m0+mm], gv1 = gv0;
    #pragma unroll
    for (int is = 0; is < 32; is++){
      gv0 += d_gpart[(size_t)(is*Bsz + 2*bp)*FFs + m0 + mm];
      gv1 += d_gpart[(size_t)(is*Bsz + 2*bp+1)*FFs + m0 + mm];
    }
    gv0 = 0.5f*gv0*(1.f + erff(gv0*0.70710678118654752f));
    gv1 = 0.5f*gv1*(1.f + erff(gv1*0.70710678118654752f));
    sbuf[n] = pk2(gv0, gv1);
  }
  __syncthreads();
  ull acc2[8];
  #pragma unroll
  for (int k = 0; k < 8; k++) acc2[k] = 0ull;
  #pragma unroll 8
  for (int mm = 0; mm < 64; mm++){
    float w = w2[(size_t)(m0+mm)*Hsz + j];
    ull wpk = pk2(w, w);
    #pragma unroll
    for (int bp = 0; bp < 8; bp++)
      acc2[bp] = ffma2(sbuf[bp*64 + mm], wpk, acc2[bp]);
  }
  #pragma unroll
  for (int bp = 0; bp < 8; bp++){
    float lo, hi; upk2(lo, hi, acc2[bp]);
    d_opart[(size_t)(ms*Bsz + 2*bp)*Hsz + j]   = lo;
    d_opart[(size_t)(ms*Bsz + 2*bp+1)*Hsz + j] = hi;
  }
}

// ============ K9: LN2 (grid 16) ============
__global__ void kln2(const float* __restrict__ b2, const float* __restrict__ g2,
                     const float* __restrict__ be2){
  __shared__ float sred[32];
  const int t = threadIdx.x, b = blockIdx.x;
  float yv[3];
  #pragma unroll
  for (int kk = 0; kk < 3; kk++){
    int j = t + 256*kk;
    float y = b2[j] + d_attn0[b*Hsz + j];
    #pragma unroll
    for (int ms = 0; ms < 48; ms++) y += d_opart[(size_t)(ms*Bsz + b)*Hsz + j];
    yv[kk] = y;
  }
  float mu = block_sum(yv[0]+yv[1]+yv[2], sred) * (1.f/Hsz);
  float ss = 0.f;
  #pragma unroll
  for (int kk = 0; kk < 3; kk++){ float d = yv[kk]-mu; ss += d*d; }
  float var = block_sum(ss, sred) * (1.f/Hsz);
  float inv = rsqrtf(var + 1e-12f);
  #pragma unroll
  for (int kk = 0; kk < 3; kk++){
    int j = t + 256*kk;
    d_hid[b*Hsz + j] = (yv[kk]-mu) * inv * g2[j] + be2[j];
  }
}

// ============ K10: pool partials (grid 144) ============
__global__ void kpool(const float* __restrict__ wp, const float* __restrict__ bp){
  __shared__ float sf[512];
  const int t = threadIdx.x, bid = blockIdx.x;
  int jc = bid % 6, ks = bid / 6;                // ks 0..23
  int j0 = jc*128, i0 = ks*32;
  #pragma unroll
  for (int k = 0; k < 2; k++){
    int v = t + 256*k;                           // 512 = 16b x 32i
    sf[v] = d_hid[(v>>5)*Hsz + i0 + (v&31)];
  }
  __syncthreads();
  int j = j0 + (t & 127), bh = t >> 7;
  float binit = (ks == 0) ? bp[j] : 0.f;
  float acc[8];
  #pragma unroll
  for (int bb = 0; bb < 8; bb++) acc[bb] = binit;
  #pragma unroll 8
  for (int i = 0; i < 32; i++){
    float w = wp[(size_t)(i0+i)*Hsz + j];
    #pragma unroll
    for (int bb = 0; bb < 8; bb++)
      acc[bb] = fmaf(sf[(bh*8+bb)*32 + i], w, acc[bb]);
  }
  #pragma unroll
  for (int bb = 0; bb < 8; bb++)
    d_pp[ks*(Bsz*Hsz) + (bh*8+bb)*Hsz + j] = acc[bb];
}

// ============ K11: tanh-pool + cls (grid 16) ============
__global__ void kcls(const float* __restrict__ wm, const float* __restrict__ bm,
                     float* __restrict__ out){
  __shared__ float sred[32];
  const int t = threadIdx.x, b = blockIdx.x;
  float contrib = 0.f;
  #pragma unroll
  for (int kk = 0; kk < 3; kk++){
    int j = t + 256*kk;
    float y = 0.f;
    #pragma unroll
    for (int ks = 0; ks < 24; ks++) y += d_pp[ks*(Bsz*Hsz) + b*Hsz + j];
    contrib += tanhf(y) * wm[j];
  }
  float c = block_sum(contrib, sred);
  if (t == 0) out[b] = c + bm[0];
}

// ---------------- launch ----------------
extern "C" void kernel_launch(void* const* d_in, const int* in_sizes, int n_in,
                              void* d_out, int out_size){
  (void)in_sizes; (void)n_in; (void)out_size;
  const float* f    = (const float*)d_in[0];
  const float* mask = (const float*)d_in[1];
  const float* wq = (const float*)d_in[2];  const float* bq = (const float*)d_in[3];
  const float* wk = (const float*)d_in[4];  const float* bk = (const float*)d_in[5];
  const float* wv = (const float*)d_in[6];  const float* bv = (const float*)d_in[7];
  const float* wo = (const float*)d_in[8];  const float* bo = (const float*)d_in[9];
  const float* g1 = (const float*)d_in[10]; const float* be1 = (const float*)d_in[11];
  const float* w1 = (const float*)d_in[12]; const float* b1 = (const float*)d_in[13];
  const float* w2 = (const float*)d_in[14]; const float* b2 = (const float*)d_in[15];
  const float* g2 = (const float*)d_in[16]; const float* be2 = (const float*)d_in[17];
  const float* wp = (const float*)d_in[18]; const float* bp = (const float*)d_in[19];
  const float* wm = (const float*)d_in[20]; const float* bm = (const float*)d_in[21];
  float* out = (float*)d_out;

  kq0p <<<256,256>>>(f, wq, bq);
  ku   <<<184,256>>>(wk, bk, wv, wo);
  kattn<<<352,256>>>(f, mask, w1, w2, wp);
  kred <<<192,256>>>();
  kctx2<<<144,256>>>(wv);
  kyp  <<<144,256>>>(wo, bv);
  kln1 <<<16, 256>>>(f, bo, g1, be1);
  kffn1<<<384,256>>>(w1);
  kffn2<<<144,256>>>(b1, w2);
  kln2 <<<16, 256>>>(b2, g2, be2);
  kpool<<<144,256>>>(wp, bp);
  kcls <<<16, 256>>>(wm, bm, out);
}

// round 13
// speedup vs baseline: 1.0827x; 1.0827x over previous
#include <cuda_runtime.h>
#include <math.h>

#define Bsz 16
#define Ssz 1024
#define Hsz 768
#define NHs 12
#define Dh  64
#define FFs 3072

// ---------------- scratch (device globals; no allocation) ----------------
__device__ float d_q0p[24*Bsz*Hsz];
__device__ float d_u[Bsz*NHs*Hsz];            // prescaled by 1/8
__device__ float d_qbk[Bsz*NHs];
__device__ float d_cmax[Bsz*NHs*16];
__device__ float d_csum[Bsz*NHs*16];
__device__ float d_fbp[16*Bsz*NHs*Hsz];
__device__ float d_fbar[Bsz*NHs*Hsz];         // normalized fbar
__device__ float d_ctxp[24*Bsz*Hsz];
__device__ float d_yp[24*Bsz*Hsz];
__device__ float d_attn0[Bsz*Hsz];
__device__ float d_gpart[32*Bsz*FFs];
__device__ float d_opart[48*Bsz*Hsz];
__device__ float d_hid[Bsz*Hsz];
__device__ float d_pp[24*Bsz*Hsz];
__device__ float d_prefsink[112*256];

typedef unsigned long long ull;

// ---------------- f32x2 packed math ----------------
__device__ __forceinline__ ull ffma2(ull a, ull b, ull c){
  ull d; asm("fma.rn.f32x2 %0, %1, %2, %3;" : "=l"(d) : "l"(a), "l"(b), "l"(c)); return d;
}
__device__ __forceinline__ ull pk2(float lo, float hi){
  ull r; asm("mov.b64 %0, {%1, %2};" : "=l"(r) : "f"(lo), "f"(hi)); return r;
}
__device__ __forceinline__ void upk2(float& lo, float& hi, ull v){
  asm("mov.b64 {%0, %1}, %2;" : "=f"(lo), "=f"(hi) : "l"(v));
}

__device__ __forceinline__ float block_sum(float v, float* red){
  int lane = threadIdx.x & 31, w = threadIdx.x >> 5;
  #pragma unroll
  for (int o = 16; o; o >>= 1) v += __shfl_xor_sync(0xffffffffu, v, o);
  if (lane == 0) red[w] = v;
  __syncthreads();
  float s = (lane < 8) ? red[lane] : 0.f;
  #pragma unroll
  for (int o = 16; o; o >>= 1) s += __shfl_xor_sync(0xffffffffu, s, o);
  __syncthreads();
  return s;
}

// grid-stride L2-warm of one tensor (prefetch blocks only)
__device__ __forceinline__ float prefsum(const float* p, int n4, int pb, int t){
  const float4* p4 = reinterpret_cast<const float4*>(p);
  float a = 0.f;
  for (int i = pb*256 + t; i < n4; i += 112*256){
    float4 v = __ldg(p4 + i);
    a += v.x + v.y + v.z + v.w;
  }
  return a;
}

// ============ K1: q0 partials (144 compute blocks) + weight prefetch (112) ============
__global__ void kq0p(const float* __restrict__ f, const float* __restrict__ wq,
                     const float* __restrict__ bq,
                     const float* __restrict__ wk, const float* __restrict__ wv,
                     const float* __restrict__ wo, const float* __restrict__ w1,
                     const float* __restrict__ w2, const float* __restrict__ wp){
  __shared__ float sf[512];
  const int t = threadIdx.x, bid = blockIdx.x;
  if (bid >= 144){
    int pb = bid - 144;
    float a = 0.f;
    a += prefsum(wk, 147456, pb, t);
    a += prefsum(wv, 147456, pb, t);
    a += prefsum(wo, 147456, pb, t);
    a += prefsum(w1, 589824, pb, t);
    a += prefsum(w2, 589824, pb, t);
    a += prefsum(wp, 147456, pb, t);
    d_prefsink[pb*256 + t] = a;
    return;
  }
  int jc = bid % 6, ks = bid / 6;                // ks 0..23
  int j0 = jc*128, i0 = ks*32;
  #pragma unroll
  for (int k = 0; k < 2; k++){
    int v = t + 256*k;                           // 512 = 16b x 32i
    sf[v] = f[(size_t)(v>>5)*Ssz*Hsz + i0 + (v&31)];
  }
  __syncthreads();
  int j = j0 + (t & 127), bh = t >> 7;
  float binit = (ks == 0) ? bq[j] : 0.f;
  float acc[8];
  #pragma unroll
  for (int bb = 0; bb < 8; bb++) acc[bb] = binit;
  #pragma unroll 8
  for (int i = 0; i < 32; i++){
    float w = wq[(size_t)(i0+i)*Hsz + j];
    #pragma unroll
    for (int bb = 0; bb < 8; bb++)
      acc[bb] = fmaf(sf[(bh*8+bb)*32 + i], w, acc[bb]);
  }
  #pragma unroll
  for (int bb = 0; bb < 8; bb++)
    d_q0p[ks*(Bsz*Hsz) + (bh*8+bb)*Hsz + j] = acc[bb];
}

// ============ K2: u = Wk q0 / 8 ; qbk (grid 72) ============
__global__ void ku(const float* __restrict__ wk, const float* __restrict__ bk){
  __shared__ float sf[1024];
  const int t = threadIdx.x, bid = blockIdx.x;
  int h = bid % 12, ic = bid / 12;
  #pragma unroll
  for (int k = 0; k < 4; k++){
    int v = t + 256*k;
    float s = 0.f;
    #pragma unroll
    for (int p = 0; p < 24; p++)
      s += d_q0p[p*(Bsz*Hsz) + (v>>6)*Hsz + h*Dh + (v&63)];
    sf[v] = s;
  }
  __syncthreads();
  if (ic == 0 && t < Bsz){
    float s = 0.f;
    for (int d = 0; d < Dh; d++) s += sf[t*Dh + d]*bk[h*Dh + d];
    d_qbk[t*NHs + h] = s * 0.125f;
  }
  int i = ic*128 + (t & 127), bh = t >> 7;
  const float4* wr = reinterpret_cast<const float4*>(wk + (size_t)i*Hsz + h*Dh);
  float acc[8] = {0,0,0,0,0,0,0,0};
  #pragma unroll
  for (int d4 = 0; d4 < Dh/4; d4++){
    float4 w = wr[d4];
    #pragma unroll
    for (int bb = 0; bb < 8; bb++){
      float4 q = *reinterpret_cast<const float4*>(&sf[(bh*8+bb)*Dh + d4*4]);
      acc[bb] = fmaf(w.x,q.x, fmaf(w.y,q.y, fmaf(w.z,q.z, fmaf(w.w,q.w, acc[bb]))));
    }
  }
  #pragma unroll
  for (int bb = 0; bb < 8; bb++)
    d_u[((bh*8+bb)*NHs + h)*Hsz + i] = acc[bb] * 0.125f;
}

// ============ K3: fused scores + chunk softmax + fbar partials (grid 256) ============
__global__ void kattn(const float* __restrict__ f, const float* __restrict__ mask){
  __shared__ __align__(16) float sU[NHs*Hsz];      // 36 KB
  __shared__ __align__(16) float sS[768];
  const int t = threadIdx.x, bid = blockIdx.x;
  int sc = bid & 15, b = bid >> 4;
  const float* ubase = d_u + (size_t)b*NHs*Hsz;
  const float* fbase = f + ((size_t)b*Ssz + sc*64)*Hsz;

  #pragma unroll
  for (int k = 0; k < NHs*Hsz/256; k++) sU[t + 256*k] = ubase[t + 256*k];
  __syncthreads();

  {
    int r = t >> 2, q = t & 3;
    ull acc2[NHs];
    #pragma unroll
    for (int h = 0; h < NHs; h++) acc2[h] = 0ull;
    const float* frow = fbase + (size_t)r*Hsz + q*8;
    #pragma unroll 4
    for (int ic = 0; ic < 24; ic++){
      ulonglong2 fv0 = *reinterpret_cast<const ulonglong2*>(frow + ic*32);
      ulonglong2 fv1 = *reinterpret_cast<const ulonglong2*>(frow + ic*32 + 4);
      #pragma unroll
      for (int h = 0; h < NHs; h++){
        const ull* up = reinterpret_cast<const ull*>(&sU[h*Hsz + ic*32 + q*8]);
        acc2[h] = ffma2(fv0.x, up[0], acc2[h]);
        acc2[h] = ffma2(fv0.y, up[1], acc2[h]);
        acc2[h] = ffma2(fv1.x, up[2], acc2[h]);
        acc2[h] = ffma2(fv1.y, up[3], acc2[h]);
      }
    }
    int srow = sc*64 + r;
    float mv = mask[b*Ssz + srow];
    #pragma unroll
    for (int h = 0; h < NHs; h++){
      float lo, hi; upk2(lo, hi, acc2[h]);
      float v = lo + hi;
      v += __shfl_xor_sync(0xffffffffu, v, 1);
      v += __shfl_xor_sync(0xffffffffu, v, 2);
      if (q == 0) sS[r*NHs + h] = v + d_qbk[b*NHs + h] + mv;
    }
  }
  __syncthreads();

  if (t < 192){
    int h = t >> 4, l16 = t & 15;
    float v0 = sS[(l16   )*NHs + h], v1 = sS[(l16+16)*NHs + h];
    float v2 = sS[(l16+32)*NHs + h], v3 = sS[(l16+48)*NHs + h];
    float m = fmaxf(fmaxf(v0,v1), fmaxf(v2,v3));
    #pragma unroll
    for (int o = 1; o < 16; o <<= 1) m = fmaxf(m, __shfl_xor_sync(0xffffffffu, m, o));
    float e0 = expf(v0-m), e1 = expf(v1-m), e2 = expf(v2-m), e3 = expf(v3-m);
    float s = e0+e1+e2+e3;
    #pragma unroll
    for (int o = 1; o < 16; o <<= 1) s += __shfl_xor_sync(0xffffffffu, s, o);
    sS[(l16   )*NHs + h] = e0; sS[(l16+16)*NHs + h] = e1;
    sS[(l16+32)*NHs + h] = e2; sS[(l16+48)*NHs + h] = e3;
    if (l16 == 0){
      d_cmax[(b*NHs + h)*16 + sc] = m;
      d_csum[(b*NHs + h)*16 + sc] = s;
    }
  }
  __syncthreads();

  if (t < 192){
    ull acc2[2*NHs];
    #pragma unroll
    for (int k = 0; k < 2*NHs; k++) acc2[k] = 0ull;
    const float* fb = fbase + t*4;
    #pragma unroll 4
    for (int s = 0; s < 64; s++){
      ulonglong2 fv = *reinterpret_cast<const ulonglong2*>(fb + (size_t)s*Hsz);
      #pragma unroll
      for (int h = 0; h < NHs; h++){
        float e = sS[s*NHs + h];
        ull pp = pk2(e, e);
        acc2[2*h]   = ffma2(pp, fv.x, acc2[2*h]);
        acc2[2*h+1] = ffma2(pp, fv.y, acc2[2*h+1]);
      }
    }
    #pragma unroll
    for (int h = 0; h < NHs; h++){
      float4 o;
      upk2(o.x, o.y, acc2[2*h]);
      upk2(o.z, o.w, acc2[2*h+1]);
      *reinterpret_cast<float4*>(
        &d_fbp[((size_t)(sc*Bsz + b)*NHs + h)*Hsz + t*4]) = o;
    }
  }
}

// ============ K4a: rescale-reduce fbar partials -> d_fbar (grid 192) ============
__global__ void kred(){
  const int t = threadIdx.x, bid = blockIdx.x;   // bid = b*12 + h
  int b = bid / NHs, h = bid % NHs;
  const float* cm = &d_cmax[bid*16];
  const float* cs = &d_csum[bid*16];
  float M = cm[0];
  #pragma unroll
  for (int sc = 1; sc < 16; sc++) M = fmaxf(M, cm[sc]);
  float w[16]; float den = 0.f;
  #pragma unroll
  for (int sc = 0; sc < 16; sc++){ w[sc] = expf(cm[sc]-M); den += cs[sc]*w[sc]; }
  float invd = 1.f/den;
  #pragma unroll
  for (int sc = 0; sc < 16; sc++) w[sc] *= invd;

  if (t < 192){
    float4 acc = make_float4(0.f,0.f,0.f,0.f);
    #pragma unroll
    for (int sc = 0; sc < 16; sc++){
      float4 v = *reinterpret_cast<const float4*>(
        &d_fbp[((size_t)(sc*Bsz + b)*NHs + h)*Hsz + t*4]);
      acc.x = fmaf(w[sc], v.x, acc.x);
      acc.y = fmaf(w[sc], v.y, acc.y);
      acc.z = fmaf(w[sc], v.z, acc.z);
      acc.w = fmaf(w[sc], v.w, acc.w);
    }
    *reinterpret_cast<float4*>(&d_fbar[(size_t)bid*Hsz + t*4]) = acc;
  }
}

// ============ K4b: ctx partials via wv (grid 144) ============
__global__ void kctx2(const float* __restrict__ wv){
  __shared__ float sf[1024];
  const int t = threadIdx.x, bid = blockIdx.x;
  int jc = bid % 6, ks = bid / 6;                // ks 0..23
  int j0 = jc*128, i0 = ks*32, h0 = jc*2;
  #pragma unroll
  for (int k = 0; k < 4; k++){
    int v = t + 256*k;                           // 1024 = 16bb x 2hl x 32i
    int bb = v>>6, hl = (v>>5)&1, i = v&31;
    sf[v] = d_fbar[(size_t)(bb*NHs + h0 + hl)*Hsz + i0 + i];
  }
  __syncthreads();
  int j = j0 + (t & 127), hl = (t & 127) >> 6, bh = t >> 7;
  float acc[8] = {0,0,0,0,0,0,0,0};
  #pragma unroll 8
  for (int i = 0; i < 32; i++){
    float w = wv[(size_t)(i0+i)*Hsz + j];
    #pragma unroll
    for (int bb = 0; bb < 8; bb++)
      acc[bb] = fmaf(sf[(bh*8+bb)*64 + hl*32 + i], w, acc[bb]);
  }
  #pragma unroll
  for (int bb = 0; bb < 8; bb++)
    d_ctxp[ks*(Bsz*Hsz) + (bh*8+bb)*Hsz + j] = acc[bb];
}

// ============ K5: y partials via wo (grid 144) ============
__global__ void kyp(const float* __restrict__ wo, const float* __restrict__ bv){
  __shared__ float sf[512];
  const int t = threadIdx.x, bid = blockIdx.x;
  int jc = bid % 6, ks = bid / 6;                // ks 0..23
  int j0 = jc*128, i0 = ks*32;
  #pragma unroll
  for (int k = 0; k < 2; k++){
    int v = t + 256*k;                           // 512 = 16b x 32i
    int bb = v>>5, i = v&31;
    float s = bv[i0 + i];
    #pragma unroll
    for (int p = 0; p < 24; p++)
      s += d_ctxp[p*(Bsz*Hsz) + bb*Hsz + i0 + i];
    sf[v] = s;
  }
  __syncthreads();
  int j = j0 + (t & 127), bh = t >> 7;
  float acc[8] = {0,0,0,0,0,0,0,0};
  #pragma unroll 8
  for (int i = 0; i < 32; i++){
    float w = wo[(size_t)(i0+i)*Hsz + j];
    #pragma unroll
    for (int bb = 0; bb < 8; bb++)
      acc[bb] = fmaf(sf[(bh*8+bb)*32 + i], w, acc[bb]);
  }
  #pragma unroll
  for (int bb = 0; bb < 8; bb++)
    d_yp[ks*(Bsz*Hsz) + (bh*8+bb)*Hsz + j] = acc[bb];
}

// ============ K6: LN1 (grid 16) ============
__global__ void kln1(const float* __restrict__ f, const float* __restrict__ bo,
                     const float* __restrict__ g1, const float* __restrict__ be1){
  __shared__ float sred[32];
  const int t = threadIdx.x, b = blockIdx.x;
  float yv[3];
  #pragma unroll
  for (int kk = 0; kk < 3; kk++){
    int j = t + 256*kk;
    float y = bo[j] + f[(size_t)b*Ssz*Hsz + j];
    #pragma unroll
    for (int ks = 0; ks < 24; ks++) y += d_yp[ks*(Bsz*Hsz) + b*Hsz + j];
    yv[kk] = y;
  }
  float mu = block_sum(yv[0]+yv[1]+yv[2], sred) * (1.f/Hsz);
  float ss = 0.f;
  #pragma unroll
  for (int kk = 0; kk < 3; kk++){ float d = yv[kk]-mu; ss += d*d; }
  float var = block_sum(ss, sred) * (1.f/Hsz);
  float inv = rsqrtf(var + 1e-12f);
  #pragma unroll
  for (int kk = 0; kk < 3; kk++){
    int j = t + 256*kk;
    d_attn0[b*Hsz + j] = (yv[kk]-mu) * inv * g1[j] + be1[j];
  }
}

// ============ K7: FFN1 partials (grid 384) ============
__global__ void kffn1(const float* __restrict__ w1){
  __shared__ ull sbuf[192];
  const int t = threadIdx.x, bid = blockIdx.x;
  int mc = bid % 12, is = bid / 12;              // is 0..31
  int m = mc*256 + t, i0 = is*24;
  if (t < 192){
    int bp = t / 24, i = t % 24;
    sbuf[t] = pk2(d_attn0[(2*bp)*Hsz + i0 + i], d_attn0[(2*bp+1)*Hsz + i0 + i]);
  }
  __syncthreads();
  ull acc2[8];
  #pragma unroll
  for (int k = 0; k < 8; k++) acc2[k] = 0ull;
  #pragma unroll 8
  for (int i = 0; i < 24; i++){
    float w = w1[(size_t)(i0+i)*FFs + m];
    ull wpk = pk2(w, w);
    #pragma unroll
    for (int bp = 0; bp < 8; bp++)
      acc2[bp] = ffma2(sbuf[bp*24 + i], wpk, acc2[bp]);
  }
  #pragma unroll
  for (int bp = 0; bp < 8; bp++){
    float lo, hi; upk2(lo, hi, acc2[bp]);
    d_gpart[(size_t)(is*Bsz + 2*bp)*FFs + m]   = lo;
    d_gpart[(size_t)(is*Bsz + 2*bp+1)*FFs + m] = hi;
  }
}

// ============ K8: fused gelu-reduce + FFN2 partials (grid 144) ============
__global__ void kffn2(const float* __restrict__ b1, const float* __restrict__ w2){
  __shared__ ull sbuf[512];
  const int t = threadIdx.x, bid = blockIdx.x;
  int jc = bid % 3, ms = bid / 3;                // ms 0..47
  int j = jc*256 + t, m0 = ms*64;
  for (int n = t; n < 512; n += 256){            // 512 = 8bp x 64mm
    int bp = n >> 6, mm = n & 63;
    float gv0 = b1[m0+mm], gv1 = gv0;
    #pragma unroll
    for (int is = 0; is < 32; is++){
      gv0 += d_gpart[(size_t)(is*Bsz + 2*bp)*FFs + m0 + mm];
      gv1 += d_gpart[(size_t)(is*Bsz + 2*bp+1)*FFs + m0 + mm];
    }
    gv0 = 0.5f*gv0*(1.f + erff(gv0*0.70710678118654752f));
    gv1 = 0.5f*gv1*(1.f + erff(gv1*0.70710678118654752f));
    sbuf[n] = pk2(gv0, gv1);
  }
  __syncthreads();
  ull acc2[8];
  #pragma unroll
  for (int k = 0; k < 8; k++) acc2[k] = 0ull;
  #pragma unroll 8
  for (int mm = 0; mm < 64; mm++){
    float w = w2[(size_t)(m0+mm)*Hsz + j];
    ull wpk = pk2(w, w);
    #pragma unroll
    for (int bp = 0; bp < 8; bp++)
      acc2[bp] = ffma2(sbuf[bp*64 + mm], wpk, acc2[bp]);
  }
  #pragma unroll
  for (int bp = 0; bp < 8; bp++){
    float lo, hi; upk2(lo, hi, acc2[bp]);
    d_opart[(size_t)(ms*Bsz + 2*bp)*Hsz + j]   = lo;
    d_opart[(size_t)(ms*Bsz + 2*bp+1)*Hsz + j] = hi;
  }
}

// ============ K9: LN2 (grid 16) ============
__global__ void kln2(const float* __restrict__ b2, const float* __restrict__ g2,
                     const float* __restrict__ be2){
  __shared__ float sred[32];
  const int t = threadIdx.x, b = blockIdx.x;
  float yv[3];
  #pragma unroll
  for (int kk = 0; kk < 3; kk++){
    int j = t + 256*kk;
    float y = b2[j] + d_attn0[b*Hsz + j];
    #pragma unroll
    for (int ms = 0; ms < 48; ms++) y += d_opart[(size_t)(ms*Bsz + b)*Hsz + j];
    yv[kk] = y;
  }
  float mu = block_sum(yv[0]+yv[1]+yv[2], sred) * (1.f/Hsz);
  float ss = 0.f;
  #pragma unroll
  for (int kk = 0; kk < 3; kk++){ float d = yv[kk]-mu; ss += d*d; }
  float var = block_sum(ss, sred) * (1.f/Hsz);
  float inv = rsqrtf(var + 1e-12f);
  #pragma unroll
  for (int kk = 0; kk < 3; kk++){
    int j = t + 256*kk;
    d_hid[b*Hsz + j] = (yv[kk]-mu) * inv * g2[j] + be2[j];
  }
}

// ============ K10: pool partials (grid 144) ============
__global__ void kpool(const float* __restrict__ wp, const float* __restrict__ bp){
  __shared__ float sf[512];
  const int t = threadIdx.x, bid = blockIdx.x;
  int jc = bid % 6, ks = bid / 6;                // ks 0..23
  int j0 = jc*128, i0 = ks*32;
  #pragma unroll
  for (int k = 0; k < 2; k++){
    int v = t + 256*k;                           // 512 = 16b x 32i
    sf[v] = d_hid[(v>>5)*Hsz + i0 + (v&31)];
  }
  __syncthreads();
  int j = j0 + (t & 127), bh = t >> 7;
  float binit = (ks == 0) ? bp[j] : 0.f;
  float acc[8];
  #pragma unroll
  for (int bb = 0; bb < 8; bb++) acc[bb] = binit;
  #pragma unroll 8
  for (int i = 0; i < 32; i++){
    float w = wp[(size_t)(i0+i)*Hsz + j];
    #pragma unroll
    for (int bb = 0; bb < 8; bb++)
      acc[bb] = fmaf(sf[(bh*8+bb)*32 + i], w, acc[bb]);
  }
  #pragma unroll
  for (int bb = 0; bb < 8; bb++)
    d_pp[ks*(Bsz*Hsz) + (bh*8+bb)*Hsz + j] = acc[bb];
}

// ============ K11: tanh-pool + cls (grid 16) ============
__global__ void kcls(const float* __restrict__ wm, const float* __restrict__ bm,
                     float* __restrict__ out){
  __shared__ float sred[32];
  const int t = threadIdx.x, b = blockIdx.x;
  float contrib = 0.f;
  #pragma unroll
  for (int kk = 0; kk < 3; kk++){
    int j = t + 256*kk;
    float y = 0.f;
    #pragma unroll
    for (int ks = 0; ks < 24; ks++) y += d_pp[ks*(Bsz*Hsz) + b*Hsz + j];
    contrib += tanhf(y) * wm[j];
  }
  float c = block_sum(contrib, sred);
  if (t == 0) out[b] = c + bm[0];
}

// ---------------- launch ----------------
extern "C" void kernel_launch(void* const* d_in, const int* in_sizes, int n_in,
                              void* d_out, int out_size){
  (void)in_sizes; (void)n_in; (void)out_size;
  const float* f    = (const float*)d_in[0];
  const float* mask = (const float*)d_in[1];
  const float* wq = (const float*)d_in[2];  const float* bq = (const float*)d_in[3];
  const float* wk = (const float*)d_in[4];  const float* bk = (const float*)d_in[5];
  const float* wv = (const float*)d_in[6];  const float* bv = (const float*)d_in[7];
  const float* wo = (const float*)d_in[8];  const float* bo = (const float*)d_in[9];
  const float* g1 = (const float*)d_in[10]; const float* be1 = (const float*)d_in[11];
  const float* w1 = (const float*)d_in[12]; const float* b1 = (const float*)d_in[13];
  const float* w2 = (const float*)d_in[14]; const float* b2 = (const float*)d_in[15];
  const float* g2 = (const float*)d_in[16]; const float* be2 = (const float*)d_in[17];
  const float* wp = (const float*)d_in[18]; const float* bp = (const float*)d_in[19];
  const float* wm = (const float*)d_in[20]; const float* bm = (const float*)d_in[21];
  float* out = (float*)d_out;

  kq0p <<<256,256>>>(f, wq, bq, wk, wv, wo, w1, w2, wp);
  ku   <<<72, 256>>>(wk, bk);
  kattn<<<256,256>>>(f, mask);
  kred <<<192,256>>>();
  kctx2<<<144,256>>>(wv);
  kyp  <<<144,256>>>(wo, bv);
  kln1 <<<16, 256>>>(f, bo, g1, be1);
  kffn1<<<384,256>>>(w1);
  kffn2<<<144,256>>>(b1, w2);
  kln2 <<<16, 256>>>(b2, g2, be2);
  kpool<<<144,256>>>(wp, bp);
  kcls <<<16, 256>>>(wm, bm, out);
}